// round 16
// baseline (speedup 1.0000x reference)
#include <cuda_runtime.h>
#include <cuda_bf16.h>
#include <cuda_fp16.h>
#include <math.h>
#include <stdint.h>

// Problem dims (fixed by the reference)
#define NN 4096
#define DD 1024
#define GC1 1024
#define GC2 1024
#define FC1 512
#define NCLS 2
#define FW 8
#define BW 8

// ---------------- scratch (device globals; no dynamic allocation) ----------
__device__ float g_bufA[(size_t)NN * GC1 / 2];  // GEMM C (fp16, normal layout)
__device__ float g_bufB[(size_t)NN * GC1 / 2];  // permuted fp16 H for GEMM2
__device__ float g_bufX[(size_t)NN * DD / 2];   // permuted fp16 x
__device__ float g_wT1[(size_t)DD * GC1 / 2];   // permuted fp16 W1
__device__ float g_wT2[(size_t)DD * GC1 / 2];   // permuted fp16 W2
__device__ float g_part[128 * GC2];
__device__ float g_zpart[16 * FC1];

// ---------------- helpers ---------------------------------------------------
__device__ __forceinline__ float selu_f(float x) {
    const float scale = 1.0507009873554805f;
    const float alpha = 1.6732632423543772f;
    return x > 0.0f ? scale * x : scale * alpha * (expf(x) - 1.0f);
}

__device__ __forceinline__ uint32_t smem_u32(const void* p) {
    uint32_t a;
    asm("{ .reg .u64 t; cvta.to.shared.u64 t, %1; cvt.u32.u64 %0, t; }"
        : "=r"(a) : "l"(p));
    return a;
}

__device__ __forceinline__ uint32_t f2h2(float a, float b) {
    __half2 h = __floats2half2_rn(a, b);
    return *(uint32_t*)&h;
}

// fp16 MMA m16n8k16, f32 accumulate. Non-volatile: pure register computation.
__device__ __forceinline__ void mma_f16(float* d, const uint4& a,
                                        uint32_t b0, uint32_t b1) {
    asm("mma.sync.aligned.m16n8k16.row.col.f32.f16.f16.f32 "
        "{%0,%1,%2,%3}, {%4,%5,%6,%7}, {%8,%9}, {%0,%1,%2,%3};"
        : "+f"(d[0]), "+f"(d[1]), "+f"(d[2]), "+f"(d[3])
        : "r"(a.x), "r"(a.y), "r"(a.z), "r"(a.w), "r"(b0), "r"(b1));
}

// closed-form inverse sqrt degree
__device__ __forceinline__ float dinv_f(int i, const float* fw, const float* bw) {
    float d = 1.0f;
#pragma unroll
    for (int j = 0; j < FW; j++) if (i + j + 1 < NN) d += fw[j];
#pragma unroll
    for (int j = 0; j < BW; j++) if (i - j - 1 >= 0) d += bw[j];
    return rsqrtf(d);
}

// ---------------- fused permute: X + W1 + W2 in one launch -------------------
// blocks [0,2048): permX ; [2048,3072): W1 ; [3072,4096): W2
__global__ __launch_bounds__(256)
void perm_all_kernel(const float* __restrict__ x,
                     const float* __restrict__ w1, const float* __restrict__ w2,
                     uint4* __restrict__ outX,
                     uint4* __restrict__ outW1, uint4* __restrict__ outW2) {
    if (blockIdx.x < 2048) {
        int g = blockIdx.x * 256 + threadIdx.x;   // 0 .. 524287
        int lane = g & 31;
        int K16 = (g >> 5) & 63;
        int R = g >> 11;
        int r = lane >> 2, c = lane & 3;
        const float* p = x + (size_t)(R * 16 + r) * 1024 + K16 * 16 + 2 * c;
        uint4 v;
        v.x = f2h2(p[0], p[1]);
        v.y = f2h2(p[8192], p[8193]);       // row + 8
        v.z = f2h2(p[8], p[9]);             // k + 8
        v.w = f2h2(p[8200], p[8201]);
        outX[g] = v;
    } else {
        int b = blockIdx.x - 2048;
        const float* W = (b < 1024) ? w1 : w2;
        uint4* out = (b < 1024) ? outW1 : outW2;
        b &= 1023;
        int bxB = b & 31, byB = b >> 5;
        __shared__ float t[32][33];
        int bx = bxB * 32, by = byB * 32;  // bx: n base, by: k base
        int tx = threadIdx.x % 32, ty = threadIdx.x / 32;
#pragma unroll
        for (int r = 0; r < 32; r += 8)
            t[ty + r][tx] = W[(size_t)(by + ty + r) * 1024 + bx + tx];  // t[k][n]
        __syncthreads();

        int e = threadIdx.x;
        if (e < 128) {
            int lane = e & 31;
            int K16l = (e >> 5) & 1;
            int N16l = e >> 6;
            int r = lane >> 2, c = lane & 3;
            int n = N16l * 16 + r;
            int kk = K16l * 16 + 2 * c;
            uint4 v;
            v.x = f2h2(t[kk][n],     t[kk + 1][n]);
            v.y = f2h2(t[kk + 8][n], t[kk + 9][n]);
            v.z = f2h2(t[kk][n + 8],     t[kk + 1][n + 8]);
            v.w = f2h2(t[kk + 8][n + 8], t[kk + 9][n + 8]);
            size_t gidx = ((size_t)(bxB * 2 + N16l) * 64
                           + byB * 2 + K16l) * 32 + lane;
            out[gidx] = v;
        }
    }
}

// ---------------- fp16 mma GEMM: C(half) = A @ BT^T + bias ------------------
// CTA 128x128, 128 threads (4 warps 2x2), warp tile 64x64.
// BK=32 (2 K16 steps), 3-stage cp.async, tiles 8 KB each.
#define STAGEU4 1024                       // uint4 per stage (A 512 + B 512)
#define GEMM_SMEM (3 * STAGEU4 * 16)       // 49152 B
#define NTG 32                             // 1024 / 32

__global__ __launch_bounds__(128, 2)
void f16_mma_gemm(const uint4* __restrict__ A, const uint4* __restrict__ BT,
                  const float* __restrict__ bias, __half* __restrict__ C) {
    extern __shared__ __align__(16) uint4 smem[];

    const int tid  = threadIdx.x;
    const int lane = tid & 31;
    const int wid  = tid >> 5;
    const int wmB  = (wid & 1) * 4;     // warp M base in 16-row blocks
    const int wnB  = (wid >> 1) * 4;    // warp N base in 16-col blocks

    // per-thread source pointers; advance 64 uint4 (2 K16 blocks) per tile
    const int ldoff = (tid >> 6) * 2048 + ((tid >> 5) & 1) * 32 + (tid & 31);
    const uint4* pA = A  + (size_t)blockIdx.y * 16384 + ldoff;
    const uint4* pB = BT + (size_t)blockIdx.x * 16384 + ldoff;

    auto load_tile = [&](int s) {
        uint4* sA = smem + s * STAGEU4 + tid;
        uint4* sB = sA + 512;
#pragma unroll
        for (int i = 0; i < 4; i++) {
            uint32_t da = smem_u32(sA + 128 * i);
            asm volatile("cp.async.cg.shared.global [%0], [%1], 16;"
                         :: "r"(da), "l"(pA + (size_t)i * 4096));
            uint32_t db = smem_u32(sB + 128 * i);
            asm volatile("cp.async.cg.shared.global [%0], [%1], 16;"
                         :: "r"(db), "l"(pB + (size_t)i * 4096));
        }
        pA += 64;
        pB += 64;
    };

    float acc[4][8][4];
#pragma unroll
    for (int mt = 0; mt < 4; mt++)
#pragma unroll
        for (int nt = 0; nt < 8; nt++)
#pragma unroll
            for (int i = 0; i < 4; i++) acc[mt][nt][i] = 0.0f;

    load_tile(0);
    asm volatile("cp.async.commit_group;");
    load_tile(1);
    asm volatile("cp.async.commit_group;");

    for (int t = 0; t < NTG; t++) {
        asm volatile("cp.async.wait_group 1;");
        __syncthreads();
        if (t + 2 < NTG) load_tile((t + 2) % 3);
        asm volatile("cp.async.commit_group;");

        const uint4* paw = smem + (t % 3) * STAGEU4 + wmB * 64 + lane;
        const uint4* pbw = smem + (t % 3) * STAGEU4 + 512 + wnB * 64 + lane;

#pragma unroll
        for (int kq = 0; kq < 2; kq++) {
            uint4 af[4], bf[4];
#pragma unroll
            for (int mt = 0; mt < 4; mt++) af[mt] = paw[mt * 64 + kq * 32];
#pragma unroll
            for (int np = 0; np < 4; np++) bf[np] = pbw[np * 64 + kq * 32];
#pragma unroll
            for (int mt = 0; mt < 4; mt++)
#pragma unroll
                for (int np = 0; np < 4; np++) {
                    mma_f16(acc[mt][2 * np],     af[mt], bf[np].x, bf[np].y);
                    mma_f16(acc[mt][2 * np + 1], af[mt], bf[np].z, bf[np].w);
                }
        }
    }

    // epilogue: register -> gmem (fp16 normal layout) with bias
    const int r = lane >> 2;
    const int c = lane & 3;
    const int gRow = blockIdx.y * 128 + wmB * 16;
    const int gCol = blockIdx.x * 128 + wnB * 16;
#pragma unroll
    for (int nt = 0; nt < 8; nt++) {
        int col = gCol + (nt >> 1) * 16 + (nt & 1) * 8 + 2 * c;
        float2 bv = *(const float2*)(bias + col);
#pragma unroll
        for (int mt = 0; mt < 4; mt++) {
            int row = gRow + mt * 16 + r;
            *(uint32_t*)(C + (size_t)row * 1024 + col) =
                f2h2(acc[mt][nt][0] + bv.x, acc[mt][nt][1] + bv.y);
            *(uint32_t*)(C + (size_t)(row + 8) * 1024 + col) =
                f2h2(acc[mt][nt][2] + bv.x, acc[mt][nt][3] + bv.y);
        }
    }
}

// ---------------- banded A-apply + SELU, sliding window ----------------------
// H is fp16 normal-layout. dinv computed inline (closed form).
// MODE 0: emit fp16 A-layout via smem staging, coalesced uint4 writes.
// MODE 1: emit per-tile column partial sums only (for mean pool).
template <int MODE>
__global__ __launch_bounds__(256)
void banded_win_kernel(const __half* __restrict__ H, void* __restrict__ outv,
                       const float* __restrict__ fw,
                       const float* __restrict__ bw) {
    __shared__ float sdv[48];
    __shared__ float scf[FW], scb[BW];
    __shared__ __half sth[8192];              // 16 KB staging (MODE 0)
    const int tid = threadIdx.x;
    const int c0  = blockIdx.y * 256;
    const int col = c0 + tid;
    const int r0  = blockIdx.x * 32;

    if (tid < 48) {
        int row = r0 - 8 + tid;
        sdv[tid] = (row >= 0 && row < NN) ? dinv_f(row, fw, bw) : 0.0f;
    } else if (tid < 56) scf[tid - 48] = fw[tid - 48];
    else if (tid < 64)   scb[tid - 56] = bw[tid - 56];
    __syncthreads();

    float hs[48];
#pragma unroll
    for (int w = 0; w < 48; w++) {
        int row = r0 - 8 + w;
        hs[w] = (row >= 0 && row < NN)
              ? __half2float(H[(size_t)row * GC1 + col]) * sdv[w] : 0.0f;
    }

    const int kk   = tid & 15;
    const int K16l = tid >> 4;
    const int laneK = (kk >> 1) & 3;
    const int jK    = (kk & 1) | ((kk >> 3) << 2);

    float psum = 0.0f;
#pragma unroll
    for (int i = 0; i < 32; i++) {
        float acc = hs[i + 8];
#pragma unroll
        for (int j = 1; j <= 8; j++) {
            acc = fmaf(scf[j - 1], hs[i + 8 + j], acc);
            acc = fmaf(scb[j - 1], hs[i + 8 - j], acc);
        }
        float v = selu_f(sdv[i + 8] * acc);
        if (MODE == 0) {
            int rr = i & 15, Rl = i >> 4;
            int lane = ((rr & 7) << 2) | laneK;
            int j = jK | ((rr >> 3) << 1);
            sth[((Rl * 16 + K16l) * 32 + lane) * 8 + j] = __float2half(v);
        } else {
            psum += v;
        }
    }

    if (MODE == 0) {
        __syncthreads();
        uint4* o4 = (uint4*)outv;
        const uint4* s4 = (const uint4*)sth;
        const int R0 = r0 >> 4;
        const int K160 = c0 >> 4;
#pragma unroll
        for (int ii = 0; ii < 4; ii++) {
            int q = tid + 256 * ii;          // 0..1023
            int b = q >> 5;                  // 0..31
            int ln = q & 31;
            o4[((size_t)(R0 + (b >> 4)) * 64 + K160 + (b & 15)) * 32 + ln] = s4[q];
        }
    } else {
        ((float*)outv)[(size_t)blockIdx.x * GC1 + col] = psum;   // g_part
    }
}

// ---------------- fused pool-reduce + FC1 GEMV (16 blocks) -------------------
// Block b owns cols c0=b*64..c0+63: reduce 128 partials -> pooled_s, then
// zpart[b][j] = sum_c pooled_s[c] * w1[(c0+c)*FC1 + j]
__global__ __launch_bounds__(512)
void tail1_kernel(const float* __restrict__ part, const float* __restrict__ w1,
                  float* __restrict__ zpart) {
    __shared__ float pooled_s[64];
    const int tid = threadIdx.x;
    const int c0 = blockIdx.x * 64;

    {
        int cl = tid >> 3;            // 0..63
        int pg = tid & 7;             // 0..7
        float s = 0.f;
#pragma unroll
        for (int p = 0; p < 16; p++)
            s += part[(size_t)(pg + p * 8) * GC2 + c0 + cl];
        s += __shfl_down_sync(0xFFFFFFFF, s, 4);
        s += __shfl_down_sync(0xFFFFFFFF, s, 2);
        s += __shfl_down_sync(0xFFFFFFFF, s, 1);
        if (pg == 0) pooled_s[cl] = s * (1.0f / NN);
    }
    __syncthreads();

    int j = tid;
    float s = 0.f;
#pragma unroll 8
    for (int c = 0; c < 64; c++)
        s = fmaf(pooled_s[c], w1[(size_t)(c0 + c) * FC1 + j], s);
    zpart[blockIdx.x * FC1 + j] = s;
}

__global__ __launch_bounds__(512)
void head2_kernel(const float* __restrict__ zpart,
                  const float* __restrict__ b1,
                  const float* __restrict__ w2, const float* __restrict__ b2,
                  float* __restrict__ out) {
    __shared__ float z[FC1];
    __shared__ float p0s[64], p1s[64];
    int j = threadIdx.x;

    float s = b1[j];
#pragma unroll
    for (int b = 0; b < 16; b++)
        s += zpart[b * FC1 + j];
    z[j] = selu_f(s);
    __syncthreads();

    if (j < 64) {
        float a0 = 0.f, a1 = 0.f;
        for (int t = j; t < FC1; t += 64) {
            a0 = fmaf(z[t], w2[t * NCLS + 0], a0);
            a1 = fmaf(z[t], w2[t * NCLS + 1], a1);
        }
        p0s[j] = a0; p1s[j] = a1;
    }
    __syncthreads();

    if (j == 0) {
        float a0 = b2[0], a1 = b2[1];
        for (int t = 0; t < 64; t++) { a0 += p0s[t]; a1 += p1s[t]; }
        out[0] = a0; out[1] = a1;
    }
}

// ---------------- launch -----------------------------------------------------
extern "C" void kernel_launch(void* const* d_in, const int* in_sizes, int n_in,
                              void* d_out, int out_size) {
    const float* x     = (const float*)d_in[0];
    const float* fw_w  = (const float*)d_in[1];
    const float* bw_w  = (const float*)d_in[2];
    const float* gc_w1 = (const float*)d_in[3];
    const float* gc_b1 = (const float*)d_in[4];
    const float* gc_w2 = (const float*)d_in[5];
    const float* gc_b2 = (const float*)d_in[6];
    const float* fc_w1 = (const float*)d_in[7];
    const float* fc_b1 = (const float*)d_in[8];
    const float* fc_w2 = (const float*)d_in[9];
    const float* fc_b2 = (const float*)d_in[10];
    float* out = (float*)d_out;

    float *bufA, *bufB, *bufX, *wT1, *wT2, *part, *zpart;
    cudaGetSymbolAddress((void**)&bufA,  g_bufA);
    cudaGetSymbolAddress((void**)&bufB,  g_bufB);
    cudaGetSymbolAddress((void**)&bufX,  g_bufX);
    cudaGetSymbolAddress((void**)&wT1,   g_wT1);
    cudaGetSymbolAddress((void**)&wT2,   g_wT2);
    cudaGetSymbolAddress((void**)&part,  g_part);
    cudaGetSymbolAddress((void**)&zpart, g_zpart);

    cudaFuncSetAttribute(f16_mma_gemm,
                         cudaFuncAttributeMaxDynamicSharedMemorySize, GEMM_SMEM);

    dim3 ggrid(GC1 / 128, NN / 128);     // (8, 32)
    dim3 bgrid(NN / 32, GC1 / 256);      // (128, 4)

    // all three permutes in one launch (W2 no longer blocks the mid-pipeline)
    perm_all_kernel<<<4096, 256>>>(x, gc_w1, gc_w2,
                                   (uint4*)bufX, (uint4*)wT1, (uint4*)wT2);

    // layer 1
    f16_mma_gemm<<<ggrid, 128, GEMM_SMEM>>>((const uint4*)bufX, (const uint4*)wT1,
                                            gc_b1, (__half*)bufA);
    banded_win_kernel<0><<<bgrid, 256>>>((const __half*)bufA, bufB, fw_w, bw_w);

    // layer 2 (banded output fused into pool partials)
    f16_mma_gemm<<<ggrid, 128, GEMM_SMEM>>>((const uint4*)bufB, (const uint4*)wT2,
                                            gc_b2, (__half*)bufA);
    banded_win_kernel<1><<<bgrid, 256>>>((const __half*)bufA, part, fw_w, bw_w);

    // fused pool + head
    tail1_kernel<<<16, 512>>>(part, fc_w1, zpart);
    head2_kernel<<<1, FC1>>>(zpart, fc_b1, fc_w2, fc_b2, out);
}

// round 17
// speedup vs baseline: 1.5041x; 1.5041x over previous
#include <cuda_runtime.h>
#include <cuda_bf16.h>
#include <cuda_fp16.h>
#include <math.h>
#include <stdint.h>

// Problem dims (fixed by the reference)
#define NN 4096
#define DD 1024
#define GC1 1024
#define GC2 1024
#define FC1 512
#define NCLS 2
#define FW 8
#define BW 8

// ---------------- scratch (device globals; no dynamic allocation) ----------
__device__ float g_bufA[(size_t)NN * GC1];      // GEMM C (f32, normal layout)
__device__ float g_bufB[(size_t)NN * GC1 / 2];  // permuted fp16 H for GEMM2
__device__ float g_bufX[(size_t)NN * DD / 2];   // permuted fp16 x
__device__ float g_wT1[(size_t)DD * GC1 / 2];   // permuted fp16 W1
__device__ float g_wT2[(size_t)DD * GC1 / 2];   // permuted fp16 W2
__device__ float g_part[128 * GC2];
__device__ float g_zpart[16 * FC1];

// ---------------- helpers ---------------------------------------------------
__device__ __forceinline__ float selu_f(float x) {
    const float scale = 1.0507009873554805f;
    const float alpha = 1.6732632423543772f;
    return x > 0.0f ? scale * x : scale * alpha * (expf(x) - 1.0f);
}

__device__ __forceinline__ uint32_t smem_u32(const void* p) {
    uint32_t a;
    asm("{ .reg .u64 t; cvta.to.shared.u64 t, %1; cvt.u32.u64 %0, t; }"
        : "=r"(a) : "l"(p));
    return a;
}

__device__ __forceinline__ uint32_t f2h2(float a, float b) {
    __half2 h = __floats2half2_rn(a, b);
    return *(uint32_t*)&h;
}

// fp16 MMA m16n8k16, f32 accumulate. Non-volatile: pure register computation.
__device__ __forceinline__ void mma_f16(float* d, const uint4& a,
                                        uint32_t b0, uint32_t b1) {
    asm("mma.sync.aligned.m16n8k16.row.col.f32.f16.f16.f32 "
        "{%0,%1,%2,%3}, {%4,%5,%6,%7}, {%8,%9}, {%0,%1,%2,%3};"
        : "+f"(d[0]), "+f"(d[1]), "+f"(d[2]), "+f"(d[3])
        : "r"(a.x), "r"(a.y), "r"(a.z), "r"(a.w), "r"(b0), "r"(b1));
}

// closed-form inverse sqrt degree
__device__ __forceinline__ float dinv_f(int i, const float* fw, const float* bw) {
    float d = 1.0f;
#pragma unroll
    for (int j = 0; j < FW; j++) if (i + j + 1 < NN) d += fw[j];
#pragma unroll
    for (int j = 0; j < BW; j++) if (i - j - 1 >= 0) d += bw[j];
    return rsqrtf(d);
}

// ---------------- fused permute: X + W1 + W2 in one launch -------------------
// blocks [0,2048): permX ; [2048,3072): W1 ; [3072,4096): W2
__global__ __launch_bounds__(256)
void perm_all_kernel(const float* __restrict__ x,
                     const float* __restrict__ w1, const float* __restrict__ w2,
                     uint4* __restrict__ outX,
                     uint4* __restrict__ outW1, uint4* __restrict__ outW2) {
    if (blockIdx.x < 2048) {
        int g = blockIdx.x * 256 + threadIdx.x;   // 0 .. 524287
        int lane = g & 31;
        int K16 = (g >> 5) & 63;
        int R = g >> 11;
        int r = lane >> 2, c = lane & 3;
        const float* p = x + (size_t)(R * 16 + r) * 1024 + K16 * 16 + 2 * c;
        uint4 v;
        v.x = f2h2(p[0], p[1]);
        v.y = f2h2(p[8192], p[8193]);       // row + 8
        v.z = f2h2(p[8], p[9]);             // k + 8
        v.w = f2h2(p[8200], p[8201]);
        outX[g] = v;
    } else {
        int b = blockIdx.x - 2048;
        const float* W = (b < 1024) ? w1 : w2;
        uint4* out = (b < 1024) ? outW1 : outW2;
        b &= 1023;
        int bxB = b & 31, byB = b >> 5;
        __shared__ float t[32][33];
        int bx = bxB * 32, by = byB * 32;  // bx: n base, by: k base
        int tx = threadIdx.x % 32, ty = threadIdx.x / 32;
#pragma unroll
        for (int r = 0; r < 32; r += 8)
            t[ty + r][tx] = W[(size_t)(by + ty + r) * 1024 + bx + tx];  // t[k][n]
        __syncthreads();

        int e = threadIdx.x;
        if (e < 128) {
            int lane = e & 31;
            int K16l = (e >> 5) & 1;
            int N16l = e >> 6;
            int r = lane >> 2, c = lane & 3;
            int n = N16l * 16 + r;
            int kk = K16l * 16 + 2 * c;
            uint4 v;
            v.x = f2h2(t[kk][n],     t[kk + 1][n]);
            v.y = f2h2(t[kk + 8][n], t[kk + 9][n]);
            v.z = f2h2(t[kk][n + 8],     t[kk + 1][n + 8]);
            v.w = f2h2(t[kk + 8][n + 8], t[kk + 9][n + 8]);
            size_t gidx = ((size_t)(bxB * 2 + N16l) * 64
                           + byB * 2 + K16l) * 32 + lane;
            out[gidx] = v;
        }
    }
}

// ---------------- fp16 mma GEMM: C(f32) = A @ BT^T + bias -------------------
// EXACT R15 configuration (27 us): CTA 128x128, 128 threads (4 warps 2x2),
// warp tile 64x64, BK=32 (2 K16 steps), 3-stage cp.async, f32 float2 epilogue.
#define STAGEU4 1024                       // uint4 per stage (A 512 + B 512)
#define GEMM_SMEM (3 * STAGEU4 * 16)       // 49152 B
#define NTG 32                             // 1024 / 32

__global__ __launch_bounds__(128, 2)
void f16_mma_gemm(const uint4* __restrict__ A, const uint4* __restrict__ BT,
                  const float* __restrict__ bias, float* __restrict__ C) {
    extern __shared__ __align__(16) uint4 smem[];

    const int tid  = threadIdx.x;
    const int lane = tid & 31;
    const int wid  = tid >> 5;
    const int wmB  = (wid & 1) * 4;     // warp M base in 16-row blocks
    const int wnB  = (wid >> 1) * 4;    // warp N base in 16-col blocks

    // per-thread source pointers; advance 64 uint4 (2 K16 blocks) per tile
    const int ldoff = (tid >> 6) * 2048 + ((tid >> 5) & 1) * 32 + (tid & 31);
    const uint4* pA = A  + (size_t)blockIdx.y * 16384 + ldoff;
    const uint4* pB = BT + (size_t)blockIdx.x * 16384 + ldoff;

    auto load_tile = [&](int s) {
        uint4* sA = smem + s * STAGEU4 + tid;
        uint4* sB = sA + 512;
#pragma unroll
        for (int i = 0; i < 4; i++) {
            uint32_t da = smem_u32(sA + 128 * i);
            asm volatile("cp.async.cg.shared.global [%0], [%1], 16;"
                         :: "r"(da), "l"(pA + (size_t)i * 4096));
            uint32_t db = smem_u32(sB + 128 * i);
            asm volatile("cp.async.cg.shared.global [%0], [%1], 16;"
                         :: "r"(db), "l"(pB + (size_t)i * 4096));
        }
        pA += 64;
        pB += 64;
    };

    float acc[4][8][4];
#pragma unroll
    for (int mt = 0; mt < 4; mt++)
#pragma unroll
        for (int nt = 0; nt < 8; nt++)
#pragma unroll
            for (int i = 0; i < 4; i++) acc[mt][nt][i] = 0.0f;

    load_tile(0);
    asm volatile("cp.async.commit_group;");
    load_tile(1);
    asm volatile("cp.async.commit_group;");

    for (int t = 0; t < NTG; t++) {
        asm volatile("cp.async.wait_group 1;");
        __syncthreads();
        if (t + 2 < NTG) load_tile((t + 2) % 3);
        asm volatile("cp.async.commit_group;");

        const uint4* paw = smem + (t % 3) * STAGEU4 + wmB * 64 + lane;
        const uint4* pbw = smem + (t % 3) * STAGEU4 + 512 + wnB * 64 + lane;

#pragma unroll
        for (int kq = 0; kq < 2; kq++) {
            uint4 af[4], bf[4];
#pragma unroll
            for (int mt = 0; mt < 4; mt++) af[mt] = paw[mt * 64 + kq * 32];
#pragma unroll
            for (int np = 0; np < 4; np++) bf[np] = pbw[np * 64 + kq * 32];
#pragma unroll
            for (int mt = 0; mt < 4; mt++)
#pragma unroll
                for (int np = 0; np < 4; np++) {
                    mma_f16(acc[mt][2 * np],     af[mt], bf[np].x, bf[np].y);
                    mma_f16(acc[mt][2 * np + 1], af[mt], bf[np].z, bf[np].w);
                }
        }
    }

    // epilogue: register -> gmem (f32 normal layout) with bias
    const int r = lane >> 2;
    const int c = lane & 3;
    const int gRow = blockIdx.y * 128 + wmB * 16;
    const int gCol = blockIdx.x * 128 + wnB * 16;
#pragma unroll
    for (int nt = 0; nt < 8; nt++) {
        int col = gCol + (nt >> 1) * 16 + (nt & 1) * 8 + 2 * c;
        float2 bv = *(const float2*)(bias + col);
#pragma unroll
        for (int mt = 0; mt < 4; mt++) {
            int row = gRow + mt * 16 + r;
            float2 o0 = make_float2(acc[mt][nt][0] + bv.x, acc[mt][nt][1] + bv.y);
            *(float2*)(C + (size_t)row * 1024 + col) = o0;
            float2 o1 = make_float2(acc[mt][nt][2] + bv.x, acc[mt][nt][3] + bv.y);
            *(float2*)(C + (size_t)(row + 8) * 1024 + col) = o1;
        }
    }
}

// ---------------- banded A-apply + SELU, sliding window ----------------------
// H is f32 normal-layout. dinv computed inline (closed form).
// MODE 0: emit fp16 A-layout via smem staging, coalesced uint4 writes.
// MODE 1: emit per-tile column partial sums only (for mean pool).
template <int MODE>
__global__ __launch_bounds__(256)
void banded_win_kernel(const float* __restrict__ H, void* __restrict__ outv,
                       const float* __restrict__ fw,
                       const float* __restrict__ bw) {
    __shared__ float sdv[48];
    __shared__ float scf[FW], scb[BW];
    __shared__ __half sth[8192];              // 16 KB staging (MODE 0)
    const int tid = threadIdx.x;
    const int c0  = blockIdx.y * 256;
    const int col = c0 + tid;
    const int r0  = blockIdx.x * 32;

    if (tid < 48) {
        int row = r0 - 8 + tid;
        sdv[tid] = (row >= 0 && row < NN) ? dinv_f(row, fw, bw) : 0.0f;
    } else if (tid < 56) scf[tid - 48] = fw[tid - 48];
    else if (tid < 64)   scb[tid - 56] = bw[tid - 56];
    __syncthreads();

    float hs[48];
#pragma unroll
    for (int w = 0; w < 48; w++) {
        int row = r0 - 8 + w;
        hs[w] = (row >= 0 && row < NN)
              ? H[(size_t)row * GC1 + col] * sdv[w] : 0.0f;
    }

    const int kk   = tid & 15;
    const int K16l = tid >> 4;
    const int laneK = (kk >> 1) & 3;
    const int jK    = (kk & 1) | ((kk >> 3) << 2);

    float psum = 0.0f;
#pragma unroll
    for (int i = 0; i < 32; i++) {
        float acc = hs[i + 8];
#pragma unroll
        for (int j = 1; j <= 8; j++) {
            acc = fmaf(scf[j - 1], hs[i + 8 + j], acc);
            acc = fmaf(scb[j - 1], hs[i + 8 - j], acc);
        }
        float v = selu_f(sdv[i + 8] * acc);
        if (MODE == 0) {
            int rr = i & 15, Rl = i >> 4;
            int lane = ((rr & 7) << 2) | laneK;
            int j = jK | ((rr >> 3) << 1);
            sth[((Rl * 16 + K16l) * 32 + lane) * 8 + j] = __float2half(v);
        } else {
            psum += v;
        }
    }

    if (MODE == 0) {
        __syncthreads();
        uint4* o4 = (uint4*)outv;
        const uint4* s4 = (const uint4*)sth;
        const int R0 = r0 >> 4;
        const int K160 = c0 >> 4;
#pragma unroll
        for (int ii = 0; ii < 4; ii++) {
            int q = tid + 256 * ii;          // 0..1023
            int b = q >> 5;                  // 0..31
            int ln = q & 31;
            o4[((size_t)(R0 + (b >> 4)) * 64 + K160 + (b & 15)) * 32 + ln] = s4[q];
        }
    } else {
        ((float*)outv)[(size_t)blockIdx.x * GC1 + col] = psum;   // g_part
    }
}

// ---------------- fused pool-reduce + FC1 GEMV (16 blocks) -------------------
__global__ __launch_bounds__(512)
void tail1_kernel(const float* __restrict__ part, const float* __restrict__ w1,
                  float* __restrict__ zpart) {
    __shared__ float pooled_s[64];
    const int tid = threadIdx.x;
    const int c0 = blockIdx.x * 64;

    {
        int cl = tid >> 3;            // 0..63
        int pg = tid & 7;             // 0..7
        float s = 0.f;
#pragma unroll
        for (int p = 0; p < 16; p++)
            s += part[(size_t)(pg + p * 8) * GC2 + c0 + cl];
        s += __shfl_down_sync(0xFFFFFFFF, s, 4);
        s += __shfl_down_sync(0xFFFFFFFF, s, 2);
        s += __shfl_down_sync(0xFFFFFFFF, s, 1);
        if (pg == 0) pooled_s[cl] = s * (1.0f / NN);
    }
    __syncthreads();

    int j = tid;
    float s = 0.f;
#pragma unroll 8
    for (int c = 0; c < 64; c++)
        s = fmaf(pooled_s[c], w1[(size_t)(c0 + c) * FC1 + j], s);
    zpart[blockIdx.x * FC1 + j] = s;
}

__global__ __launch_bounds__(512)
void head2_kernel(const float* __restrict__ zpart,
                  const float* __restrict__ b1,
                  const float* __restrict__ w2, const float* __restrict__ b2,
                  float* __restrict__ out) {
    __shared__ float z[FC1];
    __shared__ float p0s[64], p1s[64];
    int j = threadIdx.x;

    float s = b1[j];
#pragma unroll
    for (int b = 0; b < 16; b++)
        s += zpart[b * FC1 + j];
    z[j] = selu_f(s);
    __syncthreads();

    if (j < 64) {
        float a0 = 0.f, a1 = 0.f;
        for (int t = j; t < FC1; t += 64) {
            a0 = fmaf(z[t], w2[t * NCLS + 0], a0);
            a1 = fmaf(z[t], w2[t * NCLS + 1], a1);
        }
        p0s[j] = a0; p1s[j] = a1;
    }
    __syncthreads();

    if (j == 0) {
        float a0 = b2[0], a1 = b2[1];
        for (int t = 0; t < 64; t++) { a0 += p0s[t]; a1 += p1s[t]; }
        out[0] = a0; out[1] = a1;
    }
}

// ---------------- launch -----------------------------------------------------
extern "C" void kernel_launch(void* const* d_in, const int* in_sizes, int n_in,
                              void* d_out, int out_size) {
    const float* x     = (const float*)d_in[0];
    const float* fw_w  = (const float*)d_in[1];
    const float* bw_w  = (const float*)d_in[2];
    const float* gc_w1 = (const float*)d_in[3];
    const float* gc_b1 = (const float*)d_in[4];
    const float* gc_w2 = (const float*)d_in[5];
    const float* gc_b2 = (const float*)d_in[6];
    const float* fc_w1 = (const float*)d_in[7];
    const float* fc_b1 = (const float*)d_in[8];
    const float* fc_w2 = (const float*)d_in[9];
    const float* fc_b2 = (const float*)d_in[10];
    float* out = (float*)d_out;

    float *bufA, *bufB, *bufX, *wT1, *wT2, *part, *zpart;
    cudaGetSymbolAddress((void**)&bufA,  g_bufA);
    cudaGetSymbolAddress((void**)&bufB,  g_bufB);
    cudaGetSymbolAddress((void**)&bufX,  g_bufX);
    cudaGetSymbolAddress((void**)&wT1,   g_wT1);
    cudaGetSymbolAddress((void**)&wT2,   g_wT2);
    cudaGetSymbolAddress((void**)&part,  g_part);
    cudaGetSymbolAddress((void**)&zpart, g_zpart);

    cudaFuncSetAttribute(f16_mma_gemm,
                         cudaFuncAttributeMaxDynamicSharedMemorySize, GEMM_SMEM);

    dim3 ggrid(GC1 / 128, NN / 128);     // (8, 32)
    dim3 bgrid(NN / 32, GC1 / 256);      // (128, 4)

    // all three permutes in one launch
    perm_all_kernel<<<4096, 256>>>(x, gc_w1, gc_w2,
                                   (uint4*)bufX, (uint4*)wT1, (uint4*)wT2);

    // layer 1
    f16_mma_gemm<<<ggrid, 128, GEMM_SMEM>>>((const uint4*)bufX, (const uint4*)wT1,
                                            gc_b1, bufA);
    banded_win_kernel<0><<<bgrid, 256>>>(bufA, bufB, fw_w, bw_w);

    // layer 2 (banded output fused into pool partials)
    f16_mma_gemm<<<ggrid, 128, GEMM_SMEM>>>((const uint4*)bufB, (const uint4*)wT2,
                                            gc_b2, bufA);
    banded_win_kernel<1><<<bgrid, 256>>>(bufA, part, fw_w, bw_w);

    // fused pool + head
    tail1_kernel<<<16, 512>>>(part, fc_w1, zpart);
    head2_kernel<<<1, FC1>>>(zpart, fc_b1, fc_w2, fc_b2, out);
}